// round 1
// baseline (speedup 1.0000x reference)
#include <cuda_runtime.h>

// Scratch for the (never-taken, but correctness-preserving) full-reduction
// fallback path. Zero-initialized at load; the kernel maintains the
// "zero between launches" invariant itself.
__device__ float        g_S0[128];
__device__ float        g_S1[128];
__device__ unsigned int g_count;

#define NBITS     20
#define NSTATES   (1u << NBITS)     // 2^20
#define QUARTER_N 262144.0f         // N/4
#define HALF_N    524288.0f         // N/2
#define GRID      592               // 4 blocks / SM (148 SMs)
#define BLK       128               // one thread per W1 column in fallback

__global__ void qecm_kernel(const float* __restrict__ theta,  // [20,4] row-major
                            const float* __restrict__ W1,     // [2^20,128]
                            const float* __restrict__ b1,     // [128]
                            const float* __restrict__ W2,     // [128,20]
                            const float* __restrict__ b2,     // [20]
                            float* __restrict__ out) {        // [20]
    __shared__ float    sh_p0, sh_p1;
    __shared__ unsigned sh_mask;
    __shared__ int      sh_fast;
    const int tid = threadIdx.x;

    if (tid == 0) {
        // ---- scalar replay of the collapsed diag-gate cascade ----
        // state after each gate: state[i] = v_{bit_key(i)}
        const float c = 0.70710678118654752440f;  // 1/sqrt(2) as fp32
        float v0 = c, v1 = 0.0f;                  // H on q=0 applied to |0>
        int key = 0;
        for (int q = 1; q < NBITS; q++) {         // remaining Hadamards
            float s = QUARTER_N * (v0 + v1);      // cross-qubit: s0 == s1
            v0 =  c * s;
            v1 = -c * s;
            key = q;
            if (v0 == 0.0f && v1 == 0.0f) break;  // exact collapse (q==2)
        }
        if (v0 != 0.0f || v1 != 0.0f) {           // RX layers (skipped when zero)
            for (int k = 0; k < NBITS * 4; k++) {
                int q = k >> 2;
                float d = cosf(0.5f * theta[k]);
                float s0, s1;
                if (q == key) { s0 = HALF_N * v0;  s1 = HALF_N * v1; }
                else          { float s = QUARTER_N * (v0 + v1); s0 = s; s1 = s; }
                v0 = d * s0;  v1 = d * s1;  key = q;
                if (v0 == 0.0f && v1 == 0.0f) break;
            }
        }
        sh_p0  = v0 * v0;                         // |amp|^2 (state is real)
        sh_p1  = v1 * v1;
        sh_fast = (sh_p0 == 0.0f) && (sh_p1 == 0.0f);

        // ---- CNOT ladder as a GF(2)-linear map: bit19(sigma(i)) = parity(i & m)
        // sigma = src_1 ∘ src_2 ∘ ... (first scan step applied innermost), so
        // compose in reverse triu row-major order: L[t] ^= L[c].
        unsigned L[NBITS];
        for (int b = 0; b < NBITS; b++) L[b] = 1u << b;
        for (int cc = NBITS - 2; cc >= 0; cc--)
            for (int tt = NBITS - 1; tt > cc; tt--)
                L[tt] ^= L[cc];
        sh_mask = L[NBITS - 1];
    }
    __syncthreads();

    const float p0 = sh_p0, p1 = sh_p1;

    if (!sh_fast) {
        // Fallback: probs is two-valued => probs@W1 = p0*S0 + p1*S1 with
        // S_b[k] = sum over rows i with parity(i&mask)==b of W1[i][k].
        const unsigned m = sh_mask;
        const int k = tid;                        // column owned by this thread
        float a0 = 0.0f, a1 = 0.0f;
        for (unsigned r = blockIdx.x; r < NSTATES; r += gridDim.x) {
            float w = W1[(size_t)r * 128u + (unsigned)k];   // coalesced
            if (__popc(r & m) & 1) a1 += w; else a0 += w;
        }
        atomicAdd(&g_S0[k], a0);
        atomicAdd(&g_S1[k], a1);
        __threadfence();                          // release S before counter
    }
    __syncthreads();

    __shared__ unsigned sh_old;
    if (tid == 0) sh_old = atomicAdd(&g_count, 1u);
    __syncthreads();

    if (sh_old == gridDim.x - 1) {
        // Last block: all other blocks' S contributions are visible.
        __threadfence();
        __shared__ float h[128];
        {
            float z = fmaf(p0, g_S0[tid], fmaf(p1, g_S1[tid], b1[tid]));
            h[tid] = z > 0.0f ? z : 0.0f;         // relu(probs@W1 + b1)
        }
        __syncthreads();
        if (tid < NBITS) {
            float acc = b2[tid];
            #pragma unroll
            for (int kk = 0; kk < 128; kk++)
                acc = fmaf(h[kk], W2[kk * NBITS + tid], acc);
            out[tid] = acc;
        }
        __syncthreads();
        // Restore scratch invariants for the next graph replay.
        g_S0[tid] = 0.0f;
        g_S1[tid] = 0.0f;
        if (tid == 0) { __threadfence(); g_count = 0u; }
    }
}

extern "C" void kernel_launch(void* const* d_in, const int* in_sizes, int n_in,
                              void* d_out, int out_size) {
    // metadata order: x [1,4] (unused), theta [20,4], W1 [2^20,128],
    //                 b1 [128], W2 [128,20], b2 [20]; output float32 [1,20]
    (void)in_sizes; (void)n_in; (void)out_size;
    const float* theta = (const float*)d_in[1];
    const float* W1    = (const float*)d_in[2];
    const float* b1    = (const float*)d_in[3];
    const float* W2    = (const float*)d_in[4];
    const float* b2    = (const float*)d_in[5];
    float* out = (float*)d_out;
    qecm_kernel<<<GRID, BLK>>>(theta, W1, b1, W2, b2, out);
}

// round 2
// speedup vs baseline: 1.3383x; 1.3383x over previous
#include <cuda_runtime.h>

#define NBITS     20
#define NSTATES   (1u << NBITS)     // 2^20
#define QUARTER_N 262144.0f         // N/4
#define HALF_N    524288.0f         // N/2

// Single-block kernel. The diag-gate cascade provably collapses the state to
// exactly zero at the 3rd Hadamard (fp32-exact: v0' = c*s, v1' = -c*s are
// exact negatives, so the next cross-qubit sum s = (N/4)(v0+v1) == 0).
// Hence probs == 0 and out = relu(b1)@W2 + b2. The fallback reduction over
// W1 is kept for mathematical faithfulness but never executes.
__global__ void qecm_kernel(const float* __restrict__ theta,  // [20,4]
                            const float* __restrict__ W1,     // [2^20,128]
                            const float* __restrict__ b1,     // [128]
                            const float* __restrict__ W2,     // [128,20]
                            const float* __restrict__ b2,     // [20]
                            float* __restrict__ out) {        // [1,20]
    __shared__ float    sh_p0, sh_p1;
    __shared__ unsigned sh_mask;
    __shared__ int      sh_fast;
    __shared__ float    h[128];
    const int tid = threadIdx.x;

    if (tid == 0) {
        // ---- scalar replay of the collapsed diag-gate cascade ----
        const float c = 0.70710678118654752440f;  // 1/sqrt(2) in fp32
        float v0 = c, v1 = 0.0f;                  // H on q=0 applied to |0>
        int key = 0;
        for (int q = 1; q < NBITS; q++) {         // remaining Hadamards
            float s = QUARTER_N * (v0 + v1);      // cross-qubit: s0 == s1
            v0 =  c * s;
            v1 = -c * s;
            key = q;
            if (v0 == 0.0f && v1 == 0.0f) break;  // exact zero at q==2
        }
        if (v0 != 0.0f || v1 != 0.0f) {           // RX layers (skipped when zero)
            for (int k = 0; k < NBITS * 4; k++) {
                int q = k >> 2;
                float d = cosf(0.5f * theta[k]);
                float s0, s1;
                if (q == key) { s0 = HALF_N * v0;  s1 = HALF_N * v1; }
                else          { float s = QUARTER_N * (v0 + v1); s0 = s; s1 = s; }
                v0 = d * s0;  v1 = d * s1;  key = q;
                if (v0 == 0.0f && v1 == 0.0f) break;
            }
        }
        sh_p0   = v0 * v0;                        // state is real: |amp|^2
        sh_p1   = v1 * v1;
        sh_fast = (v0 == 0.0f) && (v1 == 0.0f);

        // CNOT ladder as GF(2)-linear map: bit_key(sigma(i)) = parity(i & m).
        // Compose in reverse triu row-major order: L[t] ^= L[c].
        unsigned L[NBITS];
        for (int b = 0; b < NBITS; b++) L[b] = 1u << b;
        for (int cc = NBITS - 2; cc >= 0; cc--)
            for (int tt = NBITS - 1; tt > cc; tt--)
                L[tt] ^= L[cc];
        sh_mask = L[NBITS - 1];
    }
    __syncthreads();

    const float p0 = sh_p0, p1 = sh_p1;
    float S0 = 0.0f, S1 = 0.0f;

    if (!sh_fast) {
        // Never-taken fallback: probs two-valued => probs@W1 = p0*S0 + p1*S1,
        // S_b[k] = sum over rows i with parity(i & mask)==b of W1[i][k].
        const unsigned m = sh_mask;
        const int k = tid;                        // this thread's W1 column
        for (unsigned r = 0; r < NSTATES; r++) {
            float w = W1[(size_t)r * 128u + (unsigned)k];
            if (__popc(r & m) & 1) S1 += w; else S0 += w;
        }
    }

    {   // h = relu(probs @ W1 + b1)   (== relu(b1) on the fast path)
        float z = fmaf(p0, S0, fmaf(p1, S1, b1[tid]));
        h[tid] = z > 0.0f ? z : 0.0f;
    }
    __syncthreads();

    if (tid < NBITS) {                            // out = h @ W2 + b2
        float acc = b2[tid];
        #pragma unroll
        for (int kk = 0; kk < 128; kk++)
            acc = fmaf(h[kk], W2[kk * NBITS + tid], acc);
        out[tid] = acc;
    }
}

extern "C" void kernel_launch(void* const* d_in, const int* in_sizes, int n_in,
                              void* d_out, int out_size) {
    // input order: x [1,4] (unused), theta [20,4], W1 [2^20,128],
    //              b1 [128], W2 [128,20], b2 [20]; output float32 [1,20]
    (void)in_sizes; (void)n_in; (void)out_size;
    const float* theta = (const float*)d_in[1];
    const float* W1    = (const float*)d_in[2];
    const float* b1    = (const float*)d_in[3];
    const float* W2    = (const float*)d_in[4];
    const float* b2    = (const float*)d_in[5];
    qecm_kernel<<<1, 128>>>(theta, W1, b1, W2, b2, (float*)d_out);
}